// round 1
// baseline (speedup 1.0000x reference)
#include <cuda_runtime.h>

// ---------------- problem constants ----------------
#define BATCH 128
#define CIN   500
#define HIN   16
#define WIN   16
#define NPIX  (BATCH*HIN*WIN)     // 32768
#define KTOP  30

#define C1 300
#define O1 34        // (16-1)*2+4
#define C2 100
#define O2 36        // 34+3-1
#define C3 3
#define O3 38        // 36+3-1

// ---------------- static device scratch ----------------
__device__ float g_l1[CIN];
__device__ float g_thr[CIN];
__device__ int   g_flag[NPIX];
__device__ int   g_cnt[NPIX];
__device__ int   g_chid[NPIX*KTOP];
__device__ float g_qval[NPIX*KTOP];

__device__ int   g_dirty1[BATCH*O1*O1];   // 147968
__device__ int   g_dirty2[BATCH*O2*O2];   // 165888
__device__ int   g_dirty3[BATCH*O3*O3];   // 184832
__device__ int   g_list1[BATCH*O1*O1];
__device__ int   g_list2[BATCH*O2*O2];
__device__ int   g_n1;
__device__ int   g_n2;

__device__ float g_delta1[BATCH*C1*O1*O1];  // 44,390,400 floats (~178 MB)
__device__ float g_delta2[BATCH*C2*O2*O2];  // 16,588,800 floats (~66 MB)

__device__ float g_base2cls[25*C2];         // pre-relu base2 per (rowcls,colcls), incl b2
__device__ float g_base3[C3*O3*O3];         // pre-relu base3 field

// ---------------- helpers ----------------
__device__ __forceinline__ float sgnf(float a) {
    return (float)((a > 0.f) - (a < 0.f));
}
__device__ __forceinline__ int warp_sum(int v) {
    #pragma unroll
    for (int o = 16; o > 0; o >>= 1) v += __shfl_xor_sync(0xffffffffu, v, o);
    return v;
}
__device__ __forceinline__ int cls36(int q) {
    // border class of a coordinate in [0,35] of a 36-wide conv2 output
    return (q == 0) ? 0 : (q == 1) ? 1 : (q <= 33) ? 2 : (q == 34) ? 3 : 4;
}

// ---------------- K0: zero scratch + compute l1/thr ----------------
__global__ void k_prep(const float* __restrict__ phi, const float* __restrict__ jumpp, int D) {
    int gid = blockIdx.x * blockDim.x + threadIdx.x;
    int stride = gridDim.x * blockDim.x;
    const int Z1 = BATCH*O1*O1, Z2 = BATCH*O2*O2, Z3 = BATCH*O3*O3;
    const int total = Z1 + Z2 + Z3 + NPIX + NPIX;
    for (int i = gid; i < total; i += stride) {
        int j = i;
        if (j < Z1) { g_dirty1[j] = 0; continue; }
        j -= Z1;
        if (j < Z2) { g_dirty2[j] = 0; continue; }
        j -= Z2;
        if (j < Z3) { g_dirty3[j] = 0; continue; }
        j -= Z3;
        if (j < NPIX) { g_flag[j] = 0; continue; }
        j -= NPIX;
        g_cnt[j] = 0;
    }
    if (gid == 0) { g_n1 = 0; g_n2 = 0; }
    if (gid < CIN) {
        float s = 0.f;
        for (int d = 0; d < D; d++) s += fabsf(phi[d*CIN + gid]);
        s += 1e-12f;
        g_l1[gid]  = s;
        g_thr[gid] = (*jumpp) * s;
    }
}

// ---------------- K1: base2 class table (conv2 of spatially-constant relu(b1)) ----------------
__global__ void k_base2(const float* __restrict__ w2, const float* __restrict__ b1,
                        const float* __restrict__ b2) {
    int cls = blockIdx.x;             // 0..24
    int co  = threadIdx.x;
    if (co >= C2) return;
    int ch = cls / 5, cw = cls % 5;
    const int kmin[5] = {0, 0, 0, 1, 2};
    const int kmax[5] = {0, 1, 2, 2, 2};
    int h0 = kmin[ch], h1 = kmax[ch], w0 = kmin[cw], w1e = kmax[cw];
    float acc = b2[co];
    for (int ci = 0; ci < C1; ci++) {
        float y = fmaxf(b1[ci], 0.f);
        const float* wp = w2 + (size_t)ci * (C2*9) + co * 9;
        float s = 0.f;
        for (int kh = h0; kh <= h1; kh++)
            for (int kw = w0; kw <= w1e; kw++)
                s += wp[kh*3 + kw];
        acc += y * s;
    }
    g_base2cls[cls*C2 + co] = acc;
}

// ---------------- K2: base3 field (conv3 of relu(base2 field)) ----------------
__global__ void k_base3(const float* __restrict__ w3, const float* __restrict__ b3) {
    int oh = blockIdx.x;              // 0..37
    int t  = threadIdx.x;
    if (t >= C3*O3) return;
    int co = t / O3, ow = t % O3;
    int khmin = max(0, oh - 35), khmax = min(2, oh);
    int kwmin = max(0, ow - 35), kwmax = min(2, ow);
    float acc = b3[co];
    for (int ci = 0; ci < C2; ci++) {
        for (int kh = khmin; kh <= khmax; kh++) {
            int q = oh - kh; int clh = cls36(q);
            for (int kw = kwmin; kw <= kwmax; kw++) {
                int r = ow - kw; int clw = cls36(r);
                float v = fmaxf(g_base2cls[(clh*5 + clw)*C2 + ci], 0.f);
                acc += v * w3[((ci*3 + co)*3 + kh)*3 + kw];
            }
        }
    }
    g_base3[(co*O3 + oh)*O3 + ow] = acc;
}

// ---------------- K3: streaming flag pass over x (the only big-data kernel) ----------------
__global__ void k_flag(const float4* __restrict__ x4) {
    int gid = blockIdx.x * blockDim.x + threadIdx.x;
    int stride = gridDim.x * blockDim.x;
    const int n4 = BATCH*CIN*HIN*WIN/4;  // 4,096,000
    for (int i = gid; i < n4; i += stride) {
        float4 v = x4[i];
        int ehw = i >> 6;                 // element/(H*W)
        int c = ehw % CIN;
        float t = g_thr[c];
        if (fabsf(v.x) >= t || fabsf(v.y) >= t || fabsf(v.z) >= t || fabsf(v.w) >= t) {
            int b = ehw / CIN;
            int pix = b*(HIN*WIN) + ((i*4) & (HIN*WIN-1));
            atomicOr(&g_flag[pix], 1);
        }
    }
}

// ---------------- K4: exact top-30 + saturation for flagged pixels (warp per pixel) ----------------
__global__ void k_topk(const float* __restrict__ x, const float* __restrict__ jumpp) {
    const unsigned FULL = 0xffffffffu;
    int lane = threadIdx.x & 31;
    int wi   = (blockIdx.x * blockDim.x + threadIdx.x) >> 5;
    int wstride = (gridDim.x * blockDim.x) >> 5;
    for (int p = wi; p < NPIX; p += wstride) {
        if (g_flag[p] == 0) continue;       // uniform across warp
        float jump = *jumpp;
        int b = p >> 8, hw = p & 255;
        float v[16]; unsigned u[16];
        #pragma unroll
        for (int j = 0; j < 16; j++) {
            int c = lane + 32*j;
            float xv = (c < CIN) ? x[((size_t)b*CIN + c)*(HIN*WIN) + hw] : 0.f;
            v[j] = xv;
            u[j] = (c < CIN) ? __float_as_uint(fabsf(xv)) : 0u;
        }
        // radix binary search for the 30th-largest |x| (as uint bits)
        unsigned T = 0;
        for (int bit = 31; bit >= 0; bit--) {
            unsigned cand = T | (1u << bit);
            int cl = 0;
            #pragma unroll
            for (int j = 0; j < 16; j++) cl += (u[j] >= cand);
            if (warp_sum(cl) >= KTOP) T = cand;
        }
        int mg = 0;
        #pragma unroll
        for (int j = 0; j < 16; j++) mg += (u[j] > T);
        int need = KTOP - warp_sum(mg);     // ties at T to keep, by smallest index
        int cnt_out = 0, base_tie = 0;
        unsigned lmask = (1u << lane) - 1u;
        #pragma unroll
        for (int j = 0; j < 16; j++) {
            int c = lane + 32*j;
            bool inr = (c < CIN);
            bool gt  = inr && (u[j] > T);
            bool eq  = inr && (u[j] == T);
            unsigned beq = __ballot_sync(FULL, eq);
            int tpre = base_tie + __popc(beq & lmask);
            base_tie += __popc(beq);
            bool keep = gt || (eq && tpre < need);
            float s = 0.f;
            if (keep) {
                float r = v[j] / g_l1[c];
                s = 0.5f * (sgnf(r - jump) + sgnf(r + jump));
            }
            bool emit = keep && (s != 0.f);
            unsigned be = __ballot_sync(FULL, emit);
            int pos = cnt_out + __popc(be & lmask);
            if (emit) {
                g_chid[p*KTOP + pos] = c;
                g_qval[p*KTOP + pos] = s * g_l1[c];
            }
            cnt_out += __popc(be);
        }
        if (lane == 0) g_cnt[p] = cnt_out;
    }
}

// ---------------- K5: scatter dirty1 from nonzero input pixels ----------------
__global__ void k_sc1() {
    int gid = blockIdx.x * blockDim.x + threadIdx.x;
    int stride = gridDim.x * blockDim.x;
    for (int p = gid; p < NPIX; p += stride) {
        if (g_cnt[p] == 0) continue;
        int b = p >> 8, ih = (p >> 4) & 15, iw = p & 15;
        for (int kh = 0; kh < 4; kh++)
            for (int kw = 0; kw < 4; kw++) {
                int idx = (b*O1 + 2*ih + kh)*O1 + (2*iw + kw);
                if (atomicExch(&g_dirty1[idx], 1) == 0) {
                    int t = atomicAdd(&g_n1, 1);
                    g_list1[t] = idx;
                }
            }
    }
}

// ---------------- K6: conv1 delta at dirty1 positions (warp per position) ----------------
__global__ void k_conv1d(const float* __restrict__ w1, const float* __restrict__ b1) {
    int lane = threadIdx.x & 31;
    int wi   = (blockIdx.x * blockDim.x + threadIdx.x) >> 5;
    int wstride = (gridDim.x * blockDim.x) >> 5;
    int n1 = g_n1;
    for (int t = wi; t < n1; t += wstride) {
        int idx = g_list1[t];
        int b = idx / (O1*O1), rem = idx % (O1*O1);
        int oh = rem / O1, ow = rem % O1;
        float acc[10];
        #pragma unroll
        for (int k = 0; k < 10; k++) acc[k] = 0.f;
        for (int kh = (oh & 1); kh < 4; kh += 2) {
            int dh = oh - kh; if (dh < 0 || dh > 30) continue;
            int ih = dh >> 1;
            for (int kw = (ow & 1); kw < 4; kw += 2) {
                int dw = ow - kw; if (dw < 0 || dw > 30) continue;
                int iw = dw >> 1;
                int p = (b*16 + ih)*16 + iw;
                int n = g_cnt[p];
                for (int e = 0; e < n; e++) {
                    int c = g_chid[p*KTOP + e];
                    float qv = g_qval[p*KTOP + e];
                    const float* wp = w1 + (size_t)c*(C1*16) + kh*4 + kw;
                    #pragma unroll
                    for (int k = 0; k < 10; k++) {
                        int co = lane + 32*k;
                        if (co < C1) acc[k] += qv * wp[co*16];
                    }
                }
            }
        }
        #pragma unroll
        for (int k = 0; k < 10; k++) {
            int co = lane + 32*k;
            if (co < C1) {
                float bb = b1[co];
                float d = fmaxf(bb + acc[k], 0.f) - fmaxf(bb, 0.f);
                g_delta1[(((size_t)b*C1 + co)*O1 + oh)*O1 + ow] = d;
            }
        }
    }
}

// ---------------- K7: scatter dirty2 from dirty1 ----------------
__global__ void k_sc2() {
    int gid = blockIdx.x * blockDim.x + threadIdx.x;
    int stride = gridDim.x * blockDim.x;
    int n1 = g_n1;
    for (int t = gid; t < n1; t += stride) {
        int idx = g_list1[t];
        int b = idx / (O1*O1), rem = idx % (O1*O1);
        int oh = rem / O1, ow = rem % O1;
        for (int kh = 0; kh < 3; kh++)
            for (int kw = 0; kw < 3; kw++) {
                int idx2 = (b*O2 + oh + kh)*O2 + (ow + kw);
                if (atomicExch(&g_dirty2[idx2], 1) == 0) {
                    int t2 = atomicAdd(&g_n2, 1);
                    g_list2[t2] = idx2;
                }
            }
    }
}

// ---------------- K8: conv2 delta at dirty2 positions (warp per position) ----------------
__global__ void k_conv2d(const float* __restrict__ w2) {
    int lane = threadIdx.x & 31;
    int wi   = (blockIdx.x * blockDim.x + threadIdx.x) >> 5;
    int wstride = (gridDim.x * blockDim.x) >> 5;
    int n2 = g_n2;
    for (int t = wi; t < n2; t += wstride) {
        int idx = g_list2[t];
        int b = idx / (O2*O2), rem = idx % (O2*O2);
        int oh = rem / O2, ow = rem % O2;
        float acc[4] = {0.f, 0.f, 0.f, 0.f};
        for (int kh = 0; kh < 3; kh++) {
            int q = oh - kh; if (q < 0 || q > 33) continue;
            for (int kw = 0; kw < 3; kw++) {
                int r = ow - kw; if (r < 0 || r > 33) continue;
                if (!g_dirty1[(b*O1 + q)*O1 + r]) continue;
                const float* dp = g_delta1 + (size_t)b*C1*O1*O1 + q*O1 + r;
                const float* wb = w2 + kh*3 + kw;
                for (int ci = 0; ci < C1; ci++) {
                    float dv = dp[(size_t)ci*O1*O1];
                    const float* wp = wb + (size_t)ci*(C2*9);
                    #pragma unroll
                    for (int k = 0; k < 4; k++) {
                        int co = lane + 32*k;
                        if (co < C2) acc[k] += dv * wp[co*9];
                    }
                }
            }
        }
        int clh = cls36(oh), clw = cls36(ow);
        #pragma unroll
        for (int k = 0; k < 4; k++) {
            int co = lane + 32*k;
            if (co < C2) {
                float pre = g_base2cls[(clh*5 + clw)*C2 + co];
                float d = fmaxf(pre + acc[k], 0.f) - fmaxf(pre, 0.f);
                g_delta2[(((size_t)b*C2 + co)*O2 + oh)*O2 + ow] = d;
            }
        }
    }
}

// ---------------- K9: scatter dirty3 from dirty2 ----------------
__global__ void k_sc3() {
    int gid = blockIdx.x * blockDim.x + threadIdx.x;
    int stride = gridDim.x * blockDim.x;
    int n2 = g_n2;
    for (int t = gid; t < n2; t += stride) {
        int idx = g_list2[t];
        int b = idx / (O2*O2), rem = idx % (O2*O2);
        int oh = rem / O2, ow = rem % O2;
        for (int kh = 0; kh < 3; kh++)
            for (int kw = 0; kw < 3; kw++)
                g_dirty3[(b*O3 + oh + kh)*O3 + (ow + kw)] = 1;
    }
}

// ---------------- K10: final output = crop(relu(base3 + conv3(delta2))) ----------------
__global__ void k_out(const float* __restrict__ w3, float* __restrict__ out) {
    int gid = blockIdx.x * blockDim.x + threadIdx.x;
    const int total = BATCH * C3 * 32 * 32;
    if (gid >= total) return;
    int xg = gid & 31;
    int yg = (gid >> 5) & 31;
    int co = (gid >> 10) % 3;
    int b  = gid / (3*1024);
    int oh = yg + 3, ow = xg + 3;
    float v = g_base3[(co*O3 + oh)*O3 + ow];
    if (g_dirty3[(b*O3 + oh)*O3 + ow]) {
        for (int kh = 0; kh < 3; kh++) {
            int q = oh - kh;
            for (int kw = 0; kw < 3; kw++) {
                int r = ow - kw;
                if (!g_dirty2[(b*O2 + q)*O2 + r]) continue;
                for (int ci = 0; ci < C2; ci++)
                    v += g_delta2[(((size_t)b*C2 + ci)*O2 + q)*O2 + r]
                         * w3[((ci*3 + co)*3 + kh)*3 + kw];
            }
        }
    }
    out[gid] = fmaxf(v, 0.f);
}

// ---------------- launch ----------------
extern "C" void kernel_launch(void* const* d_in, const int* in_sizes, int n_in,
                              void* d_out, int out_size) {
    const float* x    = (const float*)d_in[0];
    const float* phi  = (const float*)d_in[1];
    const float* jump = (const float*)d_in[2];
    const float* w1   = (const float*)d_in[3];
    const float* b1   = (const float*)d_in[4];
    const float* w2   = (const float*)d_in[5];
    const float* b2   = (const float*)d_in[6];
    const float* w3   = (const float*)d_in[7];
    const float* b3   = (const float*)d_in[8];
    float* out = (float*)d_out;
    int D = in_sizes[1] / CIN;   // 192

    k_prep <<<1024, 256>>>(phi, jump, D);
    k_base2<<<25, 128>>>(w2, b1, b2);
    k_base3<<<38, 128>>>(w3, b3);
    k_flag <<<2048, 256>>>((const float4*)x);
    k_topk <<<1024, 256>>>(x, jump);
    k_sc1  <<<128, 256>>>();
    k_conv1d<<<512, 256>>>(w1, b1);
    k_sc2  <<<64, 256>>>();
    k_conv2d<<<512, 256>>>(w2);
    k_sc3  <<<64, 256>>>();
    k_out  <<<1536, 256>>>(w3, out);
    (void)n_in; (void)out_size;
}

// round 3
// speedup vs baseline: 8.6872x; 8.6872x over previous
#include <cuda_runtime.h>

// ---------------- problem constants ----------------
#define BATCH 128
#define CIN   500
#define HIN   16
#define WIN   16
#define NPIX  (BATCH*HIN*WIN)     // 32768
#define KTOP  30

#define C1 300
#define O1 34        // (16-1)*2+4
#define C2 100
#define O2 36        // 34+3-1
#define C3 3
#define O3 38        // 36+3-1

// ---------------- static device scratch ----------------
__device__ float g_l1[CIN];
__device__ float g_thr[CIN];
__device__ int   g_flagd[NPIX];         // dedup for candidate list
__device__ int   g_cand[NPIX];
__device__ int   g_ncand;
__device__ int   g_cnt[NPIX];
__device__ int   g_chid[NPIX*KTOP];
__device__ float g_qval[NPIX*KTOP];

__device__ int   g_dirty1[BATCH*O1*O1];   // 147968
__device__ int   g_dirty2[BATCH*O2*O2];   // 165888
__device__ int   g_dirty3[BATCH*O3*O3];   // 184832
__device__ int   g_list1[BATCH*O1*O1];
__device__ int   g_list2[BATCH*O2*O2];
__device__ int   g_n1;
__device__ int   g_n2;

__device__ float g_delta1[BATCH*C1*O1*O1];
__device__ float g_delta2[BATCH*C2*O2*O2];

__device__ float g_base2cls[25*C2];       // pre-relu base2 per (rowcls,colcls), incl b2
__device__ float g_base3[C3*O3*O3];       // pre-relu base3 field

// ---------------- helpers ----------------
__device__ __forceinline__ float sgnf(float a) {
    return (float)((a > 0.f) - (a < 0.f));
}
__device__ __forceinline__ int warp_sum(int v) {
    #pragma unroll
    for (int o = 16; o > 0; o >>= 1) v += __shfl_xor_sync(0xffffffffu, v, o);
    return v;
}
__device__ __forceinline__ int cls36(int q) {
    return (q == 0) ? 0 : (q == 1) ? 1 : (q <= 33) ? 2 : (q == 34) ? 3 : 4;
}

// ---------------- K1: init = base2 (blocks 0..99) + zero/thr (blocks 100..227) ----------------
__global__ __launch_bounds__(288) void k_init(
    const float* __restrict__ phi, const float* __restrict__ jumpp, int D,
    const float* __restrict__ w2, const float* __restrict__ b1,
    const float* __restrict__ b2)
{
    int tid = threadIdx.x;
    if (blockIdx.x < 100) {
        // ---- base2 for co = blockIdx.x ----
        // W[k] = sum_ci relu(b1[ci]) * w2[ci*900 + co*9 + k]
        int co = blockIdx.x;
        __shared__ float s_p[270];
        __shared__ float s_W[9];
        if (tid < 270) {
            int k = tid % 9;
            int cig = tid / 9;            // 0..29, each 10 ci
            float acc = 0.f;
            #pragma unroll
            for (int j = 0; j < 10; j++) {
                int ci = cig * 10 + j;
                acc += fmaxf(b1[ci], 0.f) * w2[(size_t)ci*900 + co*9 + k];
            }
            s_p[tid] = acc;
        }
        __syncthreads();
        if (tid < 9) {
            float s = 0.f;
            #pragma unroll
            for (int g = 0; g < 30; g++) s += s_p[g*9 + tid];
            s_W[tid] = s;
        }
        __syncthreads();
        if (tid < 25) {
            const int kmin[5] = {0, 0, 0, 1, 2};
            const int kmax[5] = {0, 1, 2, 2, 2};
            int ch = tid / 5, cw = tid % 5;
            float acc = b2[co];
            for (int kh = kmin[ch]; kh <= kmax[ch]; kh++)
                for (int kw = kmin[cw]; kw <= kmax[cw]; kw++)
                    acc += s_W[kh*3 + kw];
            g_base2cls[tid*C2 + co] = acc;
        }
    } else {
        // ---- zeroing + thresholds ----
        int zb = blockIdx.x - 100;                 // 0..127
        int gz = zb * 288 + tid;                   // 0..36863
        const int Z1 = BATCH*O1*O1, Z2 = BATCH*O2*O2, Z3 = BATCH*O3*O3;
        const int total = Z1 + Z2 + Z3 + NPIX + NPIX;
        for (int i = gz; i < total; i += 128*288) {
            int j = i;
            if (j < Z1) { g_dirty1[j] = 0; continue; }
            j -= Z1;
            if (j < Z2) { g_dirty2[j] = 0; continue; }
            j -= Z2;
            if (j < Z3) { g_dirty3[j] = 0; continue; }
            j -= Z3;
            if (j < NPIX) { g_flagd[j] = 0; continue; }
            j -= NPIX;
            g_cnt[j] = 0;
        }
        if (gz == 0) { g_ncand = 0; g_n1 = 0; g_n2 = 0; }
        if (gz < CIN) {
            float s = 0.f;
            for (int d = 0; d < D; d++) s += fabsf(phi[d*CIN + gz]);
            s += 1e-12f;
            g_l1[gz]  = s;
            g_thr[gz] = (*jumpp) * s;
        }
    }
}

// ---------------- K2: base3 field, smem-staged ----------------
__global__ __launch_bounds__(256) void k_base3(
    const float* __restrict__ w3, const float* __restrict__ b3)
{
    __shared__ float s_b2r[25*C2];     // relu(base2cls)
    __shared__ float s_w3[C2*C3*9];    // 2700
    int tid = threadIdx.x;
    for (int i = tid; i < 25*C2; i += 256) s_b2r[i] = fmaxf(g_base2cls[i], 0.f);
    for (int i = tid; i < C2*C3*9; i += 256) s_w3[i] = w3[i];
    __syncthreads();

    int oh = blockIdx.x;               // 0..37
    if (tid >= C3*O3) return;
    int co = tid / O3, ow = tid % O3;

    float mh[3], mw[3];
    int bh[3], bw[3];
    #pragma unroll
    for (int kh = 0; kh < 3; kh++) {
        int q = oh - kh;
        bool v = (q >= 0 && q <= 35);
        mh[kh] = v ? 1.f : 0.f;
        bh[kh] = v ? cls36(q)*5 : 0;
    }
    #pragma unroll
    for (int kw = 0; kw < 3; kw++) {
        int r = ow - kw;
        bool v = (r >= 0 && r <= 35);
        mw[kw] = v ? 1.f : 0.f;
        bw[kw] = v ? cls36(r) : 0;
    }
    float m[9]; int bi[9];
    #pragma unroll
    for (int kh = 0; kh < 3; kh++)
        #pragma unroll
        for (int kw = 0; kw < 3; kw++) {
            m[kh*3+kw]  = mh[kh]*mw[kw];
            bi[kh*3+kw] = (bh[kh]+bw[kw])*C2;
        }

    float acc = b3[co];
    for (int ci = 0; ci < C2; ci++) {
        #pragma unroll
        for (int k = 0; k < 9; k++)
            acc += m[k] * s_b2r[bi[k] + ci] * s_w3[(ci*3 + co)*9 + k];
    }
    g_base3[(co*O3 + oh)*O3 + ow] = acc;
}

// ---------------- K3: streaming candidate pass over x ----------------
// 1000 blocks x 256 threads x 16 float4 = exactly 4,096,000 float4 = 65.5 MB
__global__ __launch_bounds__(256) void k_flag(const float4* __restrict__ x4) {
    int gid = blockIdx.x * 256 + threadIdx.x;    // 0..255999
    #pragma unroll
    for (int k = 0; k < 16; k++) {
        int i = gid + k * 256000;
        float4 v = x4[i];
        int ehw = i >> 6;
        int c = ehw % CIN;
        float t = g_thr[c];
        if (fabsf(v.x) >= t || fabsf(v.y) >= t || fabsf(v.z) >= t || fabsf(v.w) >= t) {
            int b = ehw / CIN;
            int pix = b*(HIN*WIN) + ((i*4) & (HIN*WIN-1));
            if (atomicExch(&g_flagd[pix], 1) == 0) {
                int t0 = atomicAdd(&g_ncand, 1);
                g_cand[t0] = pix;
            }
        }
    }
}

// ---------------- K4: exact top-30 + saturation on candidate pixels; scatter dirty1 ----------------
__global__ __launch_bounds__(256) void k_topk(const float* __restrict__ x,
                                              const float* __restrict__ jumpp) {
    const unsigned FULL = 0xffffffffu;
    int lane = threadIdx.x & 31;
    int wi   = (blockIdx.x * blockDim.x + threadIdx.x) >> 5;
    int wstride = (gridDim.x * blockDim.x) >> 5;
    int n = g_ncand;
    float jump = *jumpp;
    for (int t = wi; t < n; t += wstride) {
        int p = g_cand[t];
        int b = p >> 8, hw = p & 255;
        float v[16]; unsigned u[16];
        #pragma unroll
        for (int j = 0; j < 16; j++) {
            int c = lane + 32*j;
            float xv = (c < CIN) ? x[((size_t)b*CIN + c)*(HIN*WIN) + hw] : 0.f;
            v[j] = xv;
            u[j] = (c < CIN) ? __float_as_uint(fabsf(xv)) : 0u;
        }
        unsigned T = 0;
        for (int bit = 31; bit >= 0; bit--) {
            unsigned cand = T | (1u << bit);
            int cl = 0;
            #pragma unroll
            for (int j = 0; j < 16; j++) cl += (u[j] >= cand);
            if (warp_sum(cl) >= KTOP) T = cand;
        }
        int mg = 0;
        #pragma unroll
        for (int j = 0; j < 16; j++) mg += (u[j] > T);
        int need = KTOP - warp_sum(mg);
        int cnt_out = 0, base_tie = 0;
        unsigned lmask = (1u << lane) - 1u;
        #pragma unroll
        for (int j = 0; j < 16; j++) {
            int c = lane + 32*j;
            bool inr = (c < CIN);
            bool gt  = inr && (u[j] > T);
            bool eq  = inr && (u[j] == T);
            unsigned beq = __ballot_sync(FULL, eq);
            int tpre = base_tie + __popc(beq & lmask);
            base_tie += __popc(beq);
            bool keep = gt || (eq && tpre < need);
            float s = 0.f;
            if (keep) {
                float r = v[j] / g_l1[c];
                s = 0.5f * (sgnf(r - jump) + sgnf(r + jump));
            }
            bool emit = keep && (s != 0.f);
            unsigned be = __ballot_sync(FULL, emit);
            int pos = cnt_out + __popc(be & lmask);
            if (emit) {
                g_chid[p*KTOP + pos] = c;
                g_qval[p*KTOP + pos] = s * g_l1[c];
            }
            cnt_out += __popc(be);
        }
        if (cnt_out > 0) {
            if (lane == 0) g_cnt[p] = cnt_out;
            int ih = (p >> 4) & 15, iw = p & 15;
            if (lane < 16) {
                int kh = lane >> 2, kw = lane & 3;
                int idx = (b*O1 + 2*ih + kh)*O1 + (2*iw + kw);
                if (atomicExch(&g_dirty1[idx], 1) == 0) {
                    int t1 = atomicAdd(&g_n1, 1);
                    g_list1[t1] = idx;
                }
            }
        }
    }
}

// ---------------- K5: conv1 delta at dirty1 positions; scatter dirty2 ----------------
__global__ __launch_bounds__(256) void k_conv1d(const float* __restrict__ w1,
                                                const float* __restrict__ b1) {
    int lane = threadIdx.x & 31;
    int wi   = (blockIdx.x * blockDim.x + threadIdx.x) >> 5;
    int wstride = (gridDim.x * blockDim.x) >> 5;
    int n1 = g_n1;
    for (int t = wi; t < n1; t += wstride) {
        int idx = g_list1[t];
        int b = idx / (O1*O1), rem = idx % (O1*O1);
        int oh = rem / O1, ow = rem % O1;
        float acc[10];
        #pragma unroll
        for (int k = 0; k < 10; k++) acc[k] = 0.f;
        for (int kh = (oh & 1); kh < 4; kh += 2) {
            int dh = oh - kh; if (dh < 0 || dh > 30) continue;
            int ih = dh >> 1;
            for (int kw = (ow & 1); kw < 4; kw += 2) {
                int dw = ow - kw; if (dw < 0 || dw > 30) continue;
                int iw = dw >> 1;
                int p = (b*16 + ih)*16 + iw;
                int nz = g_cnt[p];
                for (int e = 0; e < nz; e++) {
                    int c = g_chid[p*KTOP + e];
                    float qv = g_qval[p*KTOP + e];
                    const float* wp = w1 + (size_t)c*(C1*16) + kh*4 + kw;
                    #pragma unroll
                    for (int k = 0; k < 10; k++) {
                        int co = lane + 32*k;
                        if (co < C1) acc[k] += qv * wp[co*16];
                    }
                }
            }
        }
        #pragma unroll
        for (int k = 0; k < 10; k++) {
            int co = lane + 32*k;
            if (co < C1) {
                float bb = b1[co];
                float d = fmaxf(bb + acc[k], 0.f) - fmaxf(bb, 0.f);
                g_delta1[(((size_t)b*C1 + co)*O1 + oh)*O1 + ow] = d;
            }
        }
        if (lane < 9) {
            int kh = lane / 3, kw = lane % 3;
            int idx2 = (b*O2 + oh + kh)*O2 + (ow + kw);
            if (atomicExch(&g_dirty2[idx2], 1) == 0) {
                int t2 = atomicAdd(&g_n2, 1);
                g_list2[t2] = idx2;
            }
        }
    }
}

// ---------------- K6: conv2 delta at dirty2 positions; scatter dirty3 ----------------
__global__ __launch_bounds__(256) void k_conv2d(const float* __restrict__ w2) {
    int lane = threadIdx.x & 31;
    int wi   = (blockIdx.x * blockDim.x + threadIdx.x) >> 5;
    int wstride = (gridDim.x * blockDim.x) >> 5;
    int n2 = g_n2;
    for (int t = wi; t < n2; t += wstride) {
        int idx = g_list2[t];
        int b = idx / (O2*O2), rem = idx % (O2*O2);
        int oh = rem / O2, ow = rem % O2;
        float acc[4] = {0.f, 0.f, 0.f, 0.f};
        for (int kh = 0; kh < 3; kh++) {
            int q = oh - kh; if (q < 0 || q > 33) continue;
            for (int kw = 0; kw < 3; kw++) {
                int r = ow - kw; if (r < 0 || r > 33) continue;
                if (!g_dirty1[(b*O1 + q)*O1 + r]) continue;
                const float* dp = g_delta1 + (size_t)b*C1*O1*O1 + q*O1 + r;
                const float* wb = w2 + kh*3 + kw;
                for (int ci = 0; ci < C1; ci++) {
                    float dv = dp[(size_t)ci*O1*O1];
                    const float* wp = wb + (size_t)ci*(C2*9);
                    #pragma unroll
                    for (int k = 0; k < 4; k++) {
                        int co = lane + 32*k;
                        if (co < C2) acc[k] += dv * wp[co*9];
                    }
                }
            }
        }
        int clh = cls36(oh), clw = cls36(ow);
        #pragma unroll
        for (int k = 0; k < 4; k++) {
            int co = lane + 32*k;
            if (co < C2) {
                float pre = g_base2cls[(clh*5 + clw)*C2 + co];
                float d = fmaxf(pre + acc[k], 0.f) - fmaxf(pre, 0.f);
                g_delta2[(((size_t)b*C2 + co)*O2 + oh)*O2 + ow] = d;
            }
        }
        if (lane < 9) {
            int kh = lane / 3, kw = lane % 3;
            g_dirty3[(b*O3 + oh + kh)*O3 + (ow + kw)] = 1;
        }
    }
}

// ---------------- K7: final output = crop(relu(base3 + conv3(delta2))) ----------------
__global__ __launch_bounds__(256) void k_out(const float* __restrict__ w3,
                                             float* __restrict__ out) {
    int gid = blockIdx.x * blockDim.x + threadIdx.x;
    const int total = BATCH * C3 * 32 * 32;
    if (gid >= total) return;
    int xg = gid & 31;
    int yg = (gid >> 5) & 31;
    int co = (gid >> 10) % 3;
    int b  = gid / (3*1024);
    int oh = yg + 3, ow = xg + 3;
    float v = g_base3[(co*O3 + oh)*O3 + ow];
    if (g_dirty3[(b*O3 + oh)*O3 + ow]) {
        for (int kh = 0; kh < 3; kh++) {
            int q = oh - kh;
            for (int kw = 0; kw < 3; kw++) {
                int r = ow - kw;
                if (!g_dirty2[(b*O2 + q)*O2 + r]) continue;
                for (int ci = 0; ci < C2; ci++)
                    v += g_delta2[(((size_t)b*C2 + ci)*O2 + q)*O2 + r]
                         * w3[((ci*3 + co)*3 + kh)*3 + kw];
            }
        }
    }
    out[gid] = fmaxf(v, 0.f);
}

// ---------------- launch ----------------
extern "C" void kernel_launch(void* const* d_in, const int* in_sizes, int n_in,
                              void* d_out, int out_size) {
    const float* x    = (const float*)d_in[0];
    const float* phi  = (const float*)d_in[1];
    const float* jump = (const float*)d_in[2];
    const float* w1   = (const float*)d_in[3];
    const float* b1   = (const float*)d_in[4];
    const float* w2   = (const float*)d_in[5];
    const float* b2   = (const float*)d_in[6];
    const float* w3   = (const float*)d_in[7];
    const float* b3   = (const float*)d_in[8];
    float* out = (float*)d_out;
    int D = in_sizes[1] / CIN;   // 192

    k_init  <<<228, 288>>>(phi, jump, D, w2, b1, b2);
    k_base3 <<<38, 256>>>(w3, b3);
    k_flag  <<<1000, 256>>>((const float4*)x);
    k_topk  <<<256, 256>>>(x, jump);
    k_conv1d<<<512, 256>>>(w1, b1);
    k_conv2d<<<512, 256>>>(w2);
    k_out   <<<1536, 256>>>(w3, out);
    (void)n_in; (void)out_size;
}